// round 1
// baseline (speedup 1.0000x reference)
#include <cuda_runtime.h>
#include <math.h>

// Problem constants
#define N_TOK 16384
#define MD    2048     // model dim (K of big GEMM)
#define PD    256      // proj dim
#define NE    64       // experts
#define TM    64       // tokens per block
#define TK    16       // K tile
#define NTHREADS 256
#define CLAMP_MAX_F 4.6051701859880913680f  // log(100)

// Device-global scratch (no allocation allowed)
__device__ float g_simN[PD * NE];   // column-normalized sim, [p][e]
__device__ float g_scale;
__device__ int   g_active;

// ---------------------------------------------------------------------------
// Prep: normalize sim_matrix columns (dim=0), compute logit scale + active cnt
// ---------------------------------------------------------------------------
__global__ void prep_kernel(const float* __restrict__ sim,
                            const float* __restrict__ temp,
                            const float* __restrict__ mask) {
    int e = threadIdx.x;
    if (e < NE) {
        float s = 0.f;
        #pragma unroll 4
        for (int p = 0; p < PD; ++p) {
            float v = sim[p * NE + e];
            s = fmaf(v, v, s);
        }
        float inv = 1.0f / fmaxf(sqrtf(s), 1e-12f);
        #pragma unroll 4
        for (int p = 0; p < PD; ++p)
            g_simN[p * NE + e] = sim[p * NE + e] * inv;
    }
    if (threadIdx.x == 0) {
        g_scale = expf(fminf(temp[0], CLAMP_MAX_F));
        float a = 0.f;
        for (int i = 0; i < NE; ++i) a += mask[i];
        g_active = (int)a;
    }
}

// ---------------------------------------------------------------------------
// Fused gate kernel: GEMM1 -> row L2-norm -> GEMM2 -> scale/mask -> logits out
//                    -> softmax -> pairwise top-k count -> top_k out
//
// Shared memory layout (floats):
//   [0,        16384)  simN_s   [PD][NE]      (persistent, 64 KB)
//   [16384,    32768)  union:
//        GEMM phase: As [TK][TM] (1024) ++ Bs [TK][PD] (4096)
//        Post phase: Hs [TM][PD]          (64 KB)
//   [32768,    33280)  sc [8 warps][NE]       (2 KB)
// Total: 33280 floats = 133120 bytes dynamic smem.
// ---------------------------------------------------------------------------
__global__ void __launch_bounds__(NTHREADS, 1)
gate_kernel(const float* __restrict__ x,
            const float* __restrict__ W,
            const float* __restrict__ bias,
            const float* __restrict__ mask,
            float* __restrict__ out_logits,
            float* __restrict__ out_topk) {
    extern __shared__ float smem[];
    float* simN_s = smem;                       // [PD][NE]
    float* As     = smem + PD * NE;             // [TK][TM]
    float* Bs     = As + TK * TM;               // [TK][PD]
    float* Hs     = smem + PD * NE;             // [TM][PD]  (union w/ As,Bs)
    float* scbuf  = smem + PD * NE + TM * PD;   // [8][NE]

    const int tid  = threadIdx.x;
    const int w    = tid >> 5;      // warp 0..7, owns tokens w*8 .. w*8+7
    const int lane = tid & 31;
    const int row0 = blockIdx.x * TM;

    // Stage simN into smem (overlaps with GEMM prologue loads)
    for (int i = tid; i < PD * NE; i += NTHREADS)
        simN_s[i] = g_simN[i];

    // ------------------- GEMM1: h[TM][PD] = x_tile @ W^T -------------------
    float acc[8][8];
    #pragma unroll
    for (int i = 0; i < 8; ++i)
        #pragma unroll
        for (int j = 0; j < 8; ++j) acc[i][j] = 0.f;

    const int r = tid >> 2;   // 0..63 : token row (for X) / proj row group (for W)
    const int q = tid & 3;    // 0..3  : k-quad
    const float* xg = x + (size_t)(row0 + r) * MD + q * 4;

    float4 xa;
    float4 wb[4];
    // prologue: stage k-tile 0
    xa = *(const float4*)(xg);
    #pragma unroll
    for (int it = 0; it < 4; ++it)
        wb[it] = *(const float4*)(W + (size_t)(r + it * 64) * MD + q * 4);

    const int NKT = MD / TK;  // 128
    for (int kt = 0; kt < NKT; ++kt) {
        // commit staged tile to smem (transposed: [k][m] / [k][p])
        #pragma unroll
        for (int u = 0; u < 4; ++u)
            As[(q * 4 + u) * TM + r] = ((const float*)&xa)[u];
        #pragma unroll
        for (int it = 0; it < 4; ++it)
            #pragma unroll
            for (int u = 0; u < 4; ++u)
                Bs[(q * 4 + u) * PD + (r + it * 64)] = ((const float*)&wb[it])[u];
        __syncthreads();

        // prefetch next k-tile (latency hidden under compute)
        if (kt + 1 < NKT) {
            int k0 = (kt + 1) * TK;
            xa = *(const float4*)(xg + k0);
            #pragma unroll
            for (int it = 0; it < 4; ++it)
                wb[it] = *(const float4*)(W + (size_t)(r + it * 64) * MD + k0 + q * 4);
        }

        // compute: 16 k-steps, 8x8 micro-tile
        #pragma unroll
        for (int k = 0; k < TK; ++k) {
            float a[8], b[8];
            // a-frag: 8 contiguous tokens of this warp (broadcast across lanes)
            float4 a0 = *(const float4*)(As + k * TM + w * 8);
            float4 a1 = *(const float4*)(As + k * TM + w * 8 + 4);
            a[0] = a0.x; a[1] = a0.y; a[2] = a0.z; a[3] = a0.w;
            a[4] = a1.x; a[5] = a1.y; a[6] = a1.z; a[7] = a1.w;
            // b-frag: strided proj columns p = lane + 32*j (conflict-free)
            #pragma unroll
            for (int j = 0; j < 8; ++j) b[j] = Bs[k * PD + lane + 32 * j];
            #pragma unroll
            for (int i = 0; i < 8; ++i)
                #pragma unroll
                for (int j = 0; j < 8; ++j)
                    acc[i][j] = fmaf(a[i], b[j], acc[i][j]);
        }
        __syncthreads();
    }

    // bias add
    float bj[8];
    #pragma unroll
    for (int j = 0; j < 8; ++j) bj[j] = __ldg(bias + lane + 32 * j);
    #pragma unroll
    for (int i = 0; i < 8; ++i)
        #pragma unroll
        for (int j = 0; j < 8; ++j) acc[i][j] += bj[j];

    // ------------- row L2 normalize (intra-warp) + stage to Hs -------------
    // (Hs overlaps As/Bs; final __syncthreads of GEMM loop makes that safe.
    //  Each warp only reads back its own rows -> __syncwarp is enough.)
    #pragma unroll
    for (int i = 0; i < 8; ++i) {
        float s = 0.f;
        #pragma unroll
        for (int j = 0; j < 8; ++j) s = fmaf(acc[i][j], acc[i][j], s);
        #pragma unroll
        for (int o = 16; o > 0; o >>= 1) s += __shfl_xor_sync(0xffffffffu, s, o);
        float inv = 1.0f / fmaxf(sqrtf(s), 1e-12f);
        #pragma unroll
        for (int j = 0; j < 8; ++j)
            Hs[(w * 8 + i) * PD + lane + 32 * j] = acc[i][j] * inv;
    }
    __syncwarp();

    // ---------------- GEMM2: logits[8][64] = hn @ simN ---------------------
    const float scale  = g_scale;
    const int   active = g_active;
    const float* Hw = Hs + (w * 8) * PD;

    float lg0[8], lg1[8];
    #pragma unroll
    for (int i = 0; i < 8; ++i) { lg0[i] = 0.f; lg1[i] = 0.f; }

    for (int p = 0; p < PD; p += 4) {
        float s0[4], s1[4];
        #pragma unroll
        for (int u = 0; u < 4; ++u) {
            s0[u] = simN_s[(p + u) * NE + lane];
            s1[u] = simN_s[(p + u) * NE + lane + 32];
        }
        #pragma unroll
        for (int i = 0; i < 8; ++i) {
            float4 h4 = *(const float4*)(Hw + i * PD + p);
            lg0[i] = fmaf(h4.x, s0[0], lg0[i]);
            lg1[i] = fmaf(h4.x, s1[0], lg1[i]);
            lg0[i] = fmaf(h4.y, s0[1], lg0[i]);
            lg1[i] = fmaf(h4.y, s1[1], lg1[i]);
            lg0[i] = fmaf(h4.z, s0[2], lg0[i]);
            lg1[i] = fmaf(h4.z, s1[2], lg1[i]);
            lg0[i] = fmaf(h4.w, s0[3], lg0[i]);
            lg1[i] = fmaf(h4.w, s1[3], lg1[i]);
        }
    }

    // ------------- scale, mask, write logits; softmax; top-k ---------------
    const float m0 = __ldg(mask + lane);
    const float m1 = __ldg(mask + lane + 32);
    float* scw = scbuf + w * NE;

    #pragma unroll 1
    for (int i = 0; i < 8; ++i) {
        const int t = row0 + w * 8 + i;
        float v0 = (m0 == 0.f) ? -1e9f : lg0[i] * scale;
        float v1 = (m1 == 0.f) ? -1e9f : lg1[i] * scale;
        out_logits[(size_t)t * NE + lane]      = v0;
        out_logits[(size_t)t * NE + lane + 32] = v1;

        // softmax over 64 within the warp
        float mx = fmaxf(v0, v1);
        #pragma unroll
        for (int o = 16; o > 0; o >>= 1)
            mx = fmaxf(mx, __shfl_xor_sync(0xffffffffu, mx, o));
        float e0 = expf(v0 - mx), e1 = expf(v1 - mx);
        float sm = e0 + e1;
        #pragma unroll
        for (int o = 16; o > 0; o >>= 1)
            sm += __shfl_xor_sync(0xffffffffu, sm, o);
        float inv = 1.0f / sm;
        float sc0 = fmaf(e0, inv, 1e-14f);
        float sc1 = fmaf(e1, inv, 1e-14f);

        // pairwise prefix-of-larger sum; keep iff (strictly-preceding sum) < 1
        scw[lane]      = sc0;
        scw[lane + 32] = sc1;
        __syncwarp();
        float pre0 = 0.f, pre1 = 0.f;
        #pragma unroll
        for (int e = 0; e < NE; ++e) {
            float s = scw[e];
            bool g0 = (s > sc0) || (s == sc0 && e < lane);
            bool g1 = (s > sc1) || (s == sc1 && e < lane + 32);
            pre0 += g0 ? s : 0.f;
            pre1 += g1 ? s : 0.f;
        }
        int cnt = (pre0 < 1.0f ? 1 : 0) + (pre1 < 1.0f ? 1 : 0);
        #pragma unroll
        for (int o = 16; o > 0; o >>= 1)
            cnt += __shfl_xor_sync(0xffffffffu, cnt, o);
        if (lane == 0 && out_topk != nullptr)
            out_topk[t] = (float)min(cnt, active);
        __syncwarp();  // protect scw before next token reuses it
    }
}

// ---------------------------------------------------------------------------
extern "C" void kernel_launch(void* const* d_in, const int* in_sizes, int n_in,
                              void* d_out, int out_size) {
    const float* x    = (const float*)d_in[0];  // [16384, 2048]
    const float* W    = (const float*)d_in[1];  // [256, 2048]
    const float* b    = (const float*)d_in[2];  // [256]
    const float* sim  = (const float*)d_in[3];  // [256, 64]
    const float* temp = (const float*)d_in[4];  // [1]
    const float* mask = (const float*)d_in[5];  // [64]

    float* out = (float*)d_out;
    // Output packing: logits [N,64] f32 first, then top_k (as float) [N].
    float* out_topk = (out_size >= N_TOK * NE + N_TOK) ? (out + (size_t)N_TOK * NE)
                                                       : nullptr;

    prep_kernel<<<1, 64>>>(sim, temp, mask);

    const int smem_bytes = (PD * NE + TM * PD + 8 * NE) * (int)sizeof(float); // 133120
    cudaFuncSetAttribute(gate_kernel,
                         cudaFuncAttributeMaxDynamicSharedMemorySize, smem_bytes);
    gate_kernel<<<N_TOK / TM, NTHREADS, smem_bytes>>>(x, W, b, mask, out, out_topk);
}